// round 3
// baseline (speedup 1.0000x reference)
#include <cuda_runtime.h>
#include <cuda_bf16.h>

// Problem constants (fixed by the registry problem)
#define NMAX    100000
#define EMAX    1600000
#define IN_C    512
#define HID_C   256
#define OUT_C   64
#define KHOPS   10
#define ALPHA_F 0.1f

// ---------------------------------------------------------------------------
// Scratch (static device globals: allocation-free). Referenced ONLY from
// device code.
// ---------------------------------------------------------------------------
__device__ float g_h1[(size_t)NMAX * HID_C];     // relu(x@W1^T+b1)
__device__ float g_h0[(size_t)NMAX * OUT_C];     // MLP output (teleport)
__device__ float g_ha[(size_t)NMAX * OUT_C];     // ping
__device__ float g_hb[(size_t)NMAX * OUT_C];     // pong
__device__ float g_dinv[NMAX];
__device__ int   g_counts[NMAX];
__device__ int   g_rowptr[NMAX + 1];
__device__ int   g_cursor[NMAX];
__device__ int2  g_csr[EMAX];                    // {src, __float_as_int(dinv[src])}
__device__ int   g_is64;                         // edge_index dtype flag

// ---------------------------------------------------------------------------
// Edge dtype detection: int64 read of int32 data combines two random values
// in [0, N) -> >= N with overwhelming probability. Check 8 entries.
// ---------------------------------------------------------------------------
__global__ void detect_dtype_kernel(const void* ei, int E, int N) {
    if (threadIdx.x == 0 && blockIdx.x == 0) {
        const long long* p = (const long long*)ei;
        int is64 = 1;
        int m = (E < 8) ? E : 8;
        for (int i = 0; i < m; ++i) {
            long long v = p[i];
            if (v < 0 || v >= (long long)N) { is64 = 0; break; }
        }
        g_is64 = is64;
    }
}

__device__ __forceinline__ int edge_at(const void* ei, int idx, int E) {
    if (g_is64) return (int)((const long long*)ei)[idx];
    return ((const int*)ei)[idx];
}

// ---------------------------------------------------------------------------
// Degree / normalization / CSR build
// ---------------------------------------------------------------------------
__global__ void zero_counts_kernel(int n) {
    int i = blockIdx.x * blockDim.x + threadIdx.x;
    if (i < n) g_counts[i] = 0;
}

__global__ void count_kernel(const void* __restrict__ ei, int E) {
    int e = blockIdx.x * blockDim.x + threadIdx.x;
    if (e < E) {
        int d = edge_at(ei, E + e, E);   // dst row
        atomicAdd(&g_counts[d], 1);
    }
}

__global__ void dinv_kernel(int n) {
    int i = blockIdx.x * blockDim.x + threadIdx.x;
    if (i < n) g_dinv[i] = rsqrtf((float)g_counts[i] + 1.0f);  // +1 self-loop
}

// Single-block exclusive scan over g_counts -> g_rowptr
__global__ void scan_kernel(int n) {
    __shared__ int tsum[1024];
    int t = threadIdx.x;
    int chunk = (n + 1023) >> 10;
    int s0 = t * chunk;
    int s1 = min(s0 + chunk, n);
    int s = 0;
    for (int i = s0; i < s1; ++i) s += g_counts[i];
    tsum[t] = s;
    __syncthreads();
    for (int off = 1; off < 1024; off <<= 1) {
        int v = (t >= off) ? tsum[t - off] : 0;
        __syncthreads();
        tsum[t] += v;
        __syncthreads();
    }
    int base = (t == 0) ? 0 : tsum[t - 1];
    for (int i = s0; i < s1; ++i) {
        int c = g_counts[i];
        g_rowptr[i] = base;
        base += c;
    }
    if (t == 1023) g_rowptr[n] = tsum[1023];
}

__global__ void cursor_init_kernel(int n) {
    int i = blockIdx.x * blockDim.x + threadIdx.x;
    if (i < n) g_cursor[i] = g_rowptr[i];
}

__global__ void scatter_kernel(const void* __restrict__ ei, int E) {
    int e = blockIdx.x * blockDim.x + threadIdx.x;
    if (e < E) {
        int s = edge_at(ei, e, E);       // src row
        int d = edge_at(ei, E + e, E);   // dst row
        int pos = atomicAdd(&g_cursor[d], 1);
        g_csr[pos] = make_int2(s, __float_as_int(g_dinv[s]));
    }
}

// ---------------------------------------------------------------------------
// fp32 GEMM: C[m][n] = sum_k A[m*K+k]*B[n*K+k] + bias[n]   (TN: both K-major)
// BM=128, BN=64, BK=16, 256 threads, 8x4 microtile.
// STAGE=1: A = x (param), C = g_h1, RELU.   STAGE=2: A = g_h1, C = g_h0.
// ---------------------------------------------------------------------------
template <int STAGE>
__global__ void __launch_bounds__(256) gemm_tn_kernel(
    const float* __restrict__ Aparam, const float* __restrict__ B,
    const float* __restrict__ bias, int M, int N, int K)
{
    const float* __restrict__ A = (STAGE == 1) ? Aparam : g_h1;
    float* __restrict__ C = (STAGE == 1) ? g_h1 : g_h0;

    const int BM = 128, BN = 64, BK = 16;
    __shared__ float As[BK][BM + 4];
    __shared__ float Bs[BK][BN + 4];

    int bm = blockIdx.x * BM;
    int bn = blockIdx.y * BN;
    int tid = threadIdx.x;
    int tx = tid & 15;   // column group (4 cols)
    int ty = tid >> 4;   // row group (8 rows)

    int ar = tid >> 2;        // 0..63
    int ac = (tid & 3) * 4;   // 0,4,8,12

    float acc[8][4];
#pragma unroll
    for (int i = 0; i < 8; ++i)
#pragma unroll
        for (int j = 0; j < 4; ++j) acc[i][j] = 0.0f;

    for (int k0 = 0; k0 < K; k0 += BK) {
#pragma unroll
        for (int p = 0; p < 2; ++p) {
            int row = bm + ar + p * 64;
            float4 v = make_float4(0.f, 0.f, 0.f, 0.f);
            if (row < M) v = *(const float4*)&A[(long long)row * K + k0 + ac];
            As[ac + 0][ar + p * 64] = v.x;
            As[ac + 1][ar + p * 64] = v.y;
            As[ac + 2][ar + p * 64] = v.z;
            As[ac + 3][ar + p * 64] = v.w;
        }
        {
            int nrow = bn + ar;
            float4 v = *(const float4*)&B[(long long)nrow * K + k0 + ac];
            Bs[ac + 0][ar] = v.x;
            Bs[ac + 1][ar] = v.y;
            Bs[ac + 2][ar] = v.z;
            Bs[ac + 3][ar] = v.w;
        }
        __syncthreads();
#pragma unroll
        for (int k = 0; k < BK; ++k) {
            float a[8], b[4];
#pragma unroll
            for (int i = 0; i < 8; ++i) a[i] = As[k][ty * 8 + i];
#pragma unroll
            for (int j = 0; j < 4; ++j) b[j] = Bs[k][tx * 4 + j];
#pragma unroll
            for (int i = 0; i < 8; ++i)
#pragma unroll
                for (int j = 0; j < 4; ++j) acc[i][j] = fmaf(a[i], b[j], acc[i][j]);
        }
        __syncthreads();
    }

    float4 bv = *(const float4*)&bias[bn + tx * 4];
#pragma unroll
    for (int i = 0; i < 8; ++i) {
        int row = bm + ty * 8 + i;
        if (row >= M) continue;
        float4 v;
        v.x = acc[i][0] + bv.x;
        v.y = acc[i][1] + bv.y;
        v.z = acc[i][2] + bv.z;
        v.w = acc[i][3] + bv.w;
        if (STAGE == 1) {
            v.x = fmaxf(v.x, 0.f); v.y = fmaxf(v.y, 0.f);
            v.z = fmaxf(v.z, 0.f); v.w = fmaxf(v.w, 0.f);
        }
        *(float4*)&C[(long long)row * N + bn + tx * 4] = v;
    }
}

// ---------------------------------------------------------------------------
// Propagation: one warp per node. 64 channels = float2 per lane.
// acc = dinv[d] * ( sum_{e in CSR(d)} h[src]*dinv[src]  +  h[d]*dinv[d] )
// h_new = 0.9*acc + 0.1*h0
// ---------------------------------------------------------------------------
__global__ void __launch_bounds__(256) prop_kernel(int iter, int kTotal,
                                                   float* __restrict__ d_out,
                                                   int n)
{
    int warp = (blockIdx.x * blockDim.x + threadIdx.x) >> 5;
    if (warp >= n) return;
    int lane = threadIdx.x & 31;

    const float* hin = (iter == 0) ? g_h0 : ((iter & 1) ? g_ha : g_hb);
    float* hout = (iter == kTotal - 1) ? d_out : ((iter & 1) ? g_hb : g_ha);

    const float2* __restrict__ hin2 = (const float2*)hin;

    float di = g_dinv[warp];
    float2 hv = hin2[(long long)warp * 32 + lane];
    float accx = hv.x * di;
    float accy = hv.y * di;

    int e = g_rowptr[warp];
    int end = g_rowptr[warp + 1];

    for (; e + 4 <= end; e += 4) {
        int2 m0 = g_csr[e + 0];
        int2 m1 = g_csr[e + 1];
        int2 m2 = g_csr[e + 2];
        int2 m3 = g_csr[e + 3];
        float2 s0 = hin2[(long long)m0.x * 32 + lane];
        float2 s1 = hin2[(long long)m1.x * 32 + lane];
        float2 s2 = hin2[(long long)m2.x * 32 + lane];
        float2 s3 = hin2[(long long)m3.x * 32 + lane];
        accx = fmaf(s0.x, __int_as_float(m0.y), accx);
        accy = fmaf(s0.y, __int_as_float(m0.y), accy);
        accx = fmaf(s1.x, __int_as_float(m1.y), accx);
        accy = fmaf(s1.y, __int_as_float(m1.y), accy);
        accx = fmaf(s2.x, __int_as_float(m2.y), accx);
        accy = fmaf(s2.y, __int_as_float(m2.y), accy);
        accx = fmaf(s3.x, __int_as_float(m3.y), accx);
        accy = fmaf(s3.y, __int_as_float(m3.y), accy);
    }
    for (; e < end; ++e) {
        int2 m = g_csr[e];
        float2 s = hin2[(long long)m.x * 32 + lane];
        accx = fmaf(s.x, __int_as_float(m.y), accx);
        accy = fmaf(s.y, __int_as_float(m.y), accy);
    }

    accx *= di;
    accy *= di;
    float2 h0v = ((const float2*)g_h0)[(long long)warp * 32 + lane];
    float2 outv;
    outv.x = fmaf(1.0f - ALPHA_F, accx, ALPHA_F * h0v.x);
    outv.y = fmaf(1.0f - ALPHA_F, accy, ALPHA_F * h0v.y);
    ((float2*)hout)[(long long)warp * 32 + lane] = outv;
}

// ---------------------------------------------------------------------------
// Launch — kernel launches ONLY (graph-capturable, no host CUDA API calls).
// ---------------------------------------------------------------------------
extern "C" void kernel_launch(void* const* d_in, const int* in_sizes, int n_in,
                              void* d_out, int out_size)
{
    const float* x       = (const float*)d_in[0];
    const void*  ei      = d_in[1];               // int32 or int64, detected on device
    const float* w1      = (const float*)d_in[2];
    const float* b1      = (const float*)d_in[3];
    const float* w2      = (const float*)d_in[4];
    const float* b2      = (const float*)d_in[5];
    float* out           = (float*)d_out;

    int N = in_sizes[0] / IN_C;   // 100000
    int E = in_sizes[1] / 2;      // 1600000

    int nb = (N + 255) / 256;
    int eb = (E + 255) / 256;

    // --- graph preprocessing: dtype detect, degrees, dinv, CSR ---
    detect_dtype_kernel<<<1, 32>>>(ei, E, N);
    zero_counts_kernel<<<nb, 256>>>(N);
    count_kernel<<<eb, 256>>>(ei, E);
    dinv_kernel<<<nb, 256>>>(N);
    scan_kernel<<<1, 1024>>>(N);
    cursor_init_kernel<<<nb, 256>>>(N);
    scatter_kernel<<<eb, 256>>>(ei, E);

    // --- MLP ---
    {
        dim3 grid((N + 127) / 128, HID_C / 64);
        gemm_tn_kernel<1><<<grid, 256>>>(x, w1, b1, N, HID_C, IN_C);
    }
    {
        dim3 grid((N + 127) / 128, OUT_C / 64);
        gemm_tn_kernel<2><<<grid, 256>>>(nullptr, w2, b2, N, OUT_C, HID_C);
    }

    // --- K-hop propagation (atomic-free gathers over CSR) ---
    int pb = (N * 32 + 255) / 256;  // one warp per node
    for (int it = 0; it < KHOPS; ++it) {
        prop_kernel<<<pb, 256>>>(it, KHOPS, out, N);
    }
}